// round 1
// baseline (speedup 1.0000x reference)
#include <cuda_runtime.h>
#include <math.h>

// Problem constants
#define NR   5120        // LSTM batch (512*10)
#define HID  256
#define G4   1024        // 4*HID
#define SEQ  30
#define INP  100
#define KTOT 356         // INP + HID
#define BATCH 512

// Persistent state (re-initialized inside the graph each replay)
__device__ float g_h[2][NR * HID];
__device__ float g_c[2][NR * HID];
__device__ float g_gates[2][NR * G4];

__global__ void k_init(const float* __restrict__ h0, const float* __restrict__ c0) {
    int i = blockIdx.x * blockDim.x + threadIdx.x;
    if (i < 2 * NR * HID) {
        ((float*)g_h)[i] = h0[i];
        ((float*)g_c)[i] = c0[i];
    }
}

// Per-step gate GEMM: gates[dir] = [x_t | h(dir)] @ [W_ih(dir)^T ; W_hh(dir)^T]
// C is [NR x G4], A is [NR x 356] (virtual), B is [356 x G4] (virtual, = W^T).
// Classic 128x128 tile, 256 threads, 8x8 micro-tile, K-chunk 8.
__global__ __launch_bounds__(256) void k_gemm(
    const float* __restrict__ x,
    const float* __restrict__ WihF, const float* __restrict__ WhhF,
    const float* __restrict__ WihB, const float* __restrict__ WhhB,
    int step)
{
    const int dir = blockIdx.z;
    const float* __restrict__ Wih = dir ? WihB : WihF;
    const float* __restrict__ Whh = dir ? WhhB : WhhF;
    const float* __restrict__ h   = g_h[dir];
    const int tx = dir ? (SEQ - 1 - step) : step;
    const float* __restrict__ xb = x + tx * INP;  // + n*(SEQ*INP) + k

    __shared__ float As[8][128];
    __shared__ float Bs[8][132];   // pad to dodge worst bank conflicts

    const int row0 = blockIdx.y * 128;
    const int col0 = blockIdx.x * 128;
    const int tid = threadIdx.x;
    const int tr = tid >> 4;       // 0..15
    const int tc = tid & 15;       // 0..15

    float acc[8][8];
#pragma unroll
    for (int i = 0; i < 8; i++)
#pragma unroll
        for (int j = 0; j < 8; j++) acc[i][j] = 0.f;

    for (int k0 = 0; k0 < KTOT; k0 += 8) {
        // Load A tile: 128 rows x 8 k  (1024 elems, 4 per thread)
#pragma unroll
        for (int l = 0; l < 4; l++) {
            int idx = tid + l * 256;
            int r = idx >> 3, kk = idx & 7;
            int k = k0 + kk;
            int n = row0 + r;
            float v = 0.f;
            if (k < INP)       v = xb[n * (SEQ * INP) + k];
            else if (k < KTOT) v = h[n * HID + (k - INP)];
            As[kk][r] = v;
        }
        // Load B tile: 8 k x 128 cols, B[k][c] = W[col][k]
#pragma unroll
        for (int l = 0; l < 4; l++) {
            int idx = tid + l * 256;
            int c = idx & 127, kk = idx >> 7;
            int k = k0 + kk;
            int col = col0 + c;
            float v = 0.f;
            if (k < INP)       v = Wih[col * INP + k];
            else if (k < KTOT) v = Whh[col * HID + (k - INP)];
            Bs[kk][c] = v;
        }
        __syncthreads();
#pragma unroll
        for (int kk = 0; kk < 8; kk++) {
            float a[8], b[8];
#pragma unroll
            for (int i = 0; i < 8; i++) a[i] = As[kk][tr * 8 + i];
#pragma unroll
            for (int j = 0; j < 8; j++) b[j] = Bs[kk][tc * 8 + j];
#pragma unroll
            for (int i = 0; i < 8; i++)
#pragma unroll
                for (int j = 0; j < 8; j++)
                    acc[i][j] = fmaf(a[i], b[j], acc[i][j]);
        }
        __syncthreads();
    }

    float* __restrict__ out = g_gates[dir];
#pragma unroll
    for (int i = 0; i < 8; i++) {
        int n = row0 + tr * 8 + i;
#pragma unroll
        for (int j = 0; j < 8; j++)
            out[n * G4 + col0 + tc * 8 + j] = acc[i][j];
    }
}

__device__ __forceinline__ float sigm(float v) { return 1.f / (1.f + expf(-v)); }

// Pointwise LSTM cell update for both directions.
__global__ void k_update(const float* __restrict__ biF, const float* __restrict__ bhF,
                         const float* __restrict__ biB, const float* __restrict__ bhB)
{
    int idx = blockIdx.x * blockDim.x + threadIdx.x;
    if (idx >= 2 * NR * HID) return;
    int dir = idx / (NR * HID);
    int r   = idx - dir * (NR * HID);
    int n   = r >> 8;
    int hc  = r & 255;
    const float* __restrict__ gt = g_gates[dir] + n * G4;
    const float* __restrict__ bi = dir ? biB : biF;
    const float* __restrict__ bh = dir ? bhB : bhF;
    float gi = gt[hc]       + bi[hc]       + bh[hc];
    float gf = gt[hc + 256] + bi[hc + 256] + bh[hc + 256];
    float gg = gt[hc + 512] + bi[hc + 512] + bh[hc + 512];
    float go = gt[hc + 768] + bi[hc + 768] + bh[hc + 768];
    float c = g_c[dir][r];
    c = sigm(gf) * c + sigm(gi) * tanhf(gg);
    g_c[dir][r] = c;
    g_h[dir][r] = sigm(go) * tanhf(c);
}

// x_fea[b, j, k] = k<128 ? hF[n, k] : hB[n, k]   (n = b*10+j, k in [0,256))
__global__ void k_xfea(float* __restrict__ out_xfea) {
    int idx = blockIdx.x * blockDim.x + threadIdx.x;
    if (idx >= NR * HID) return;
    int k = idx & 255;
    int n = idx >> 8;
    out_xfea[idx] = (k < 128) ? g_h[0][n * HID + k] : g_h[1][n * HID + k];
}

// Head: z = flat @ W1^T + b1 ; logits = z @ W2^T + b2 ; softmax.
// One block per batch row, 64 threads (one per z column).
__global__ __launch_bounds__(64) void k_head(
    const float* __restrict__ W1, const float* __restrict__ b1,
    const float* __restrict__ W2, const float* __restrict__ b2,
    float* __restrict__ out)
{
    int b = blockIdx.x;
    int u = threadIdx.x;
    const float* __restrict__ flat = out + BATCH * 5 + b * 2560;
    __shared__ float z[64];
    __shared__ float logit[5];

    float acc = b1[u];
    const float* __restrict__ w = W1 + u * 2560;
#pragma unroll 4
    for (int v = 0; v < 2560; v++)
        acc = fmaf(flat[v], w[v], acc);
    z[u] = acc;
    __syncthreads();

    if (u < 5) {
        float a = b2[u];
#pragma unroll
        for (int j = 0; j < 64; j++)
            a = fmaf(z[j], W2[u * 64 + j], a);
        logit[u] = a;
    }
    __syncthreads();

    if (u == 0) {
        float m = logit[0];
#pragma unroll
        for (int p = 1; p < 5; p++) m = fmaxf(m, logit[p]);
        float e[5], s = 0.f;
#pragma unroll
        for (int p = 0; p < 5; p++) { e[p] = expf(logit[p] - m); s += e[p]; }
        float inv = 1.f / s;
#pragma unroll
        for (int p = 0; p < 5; p++) out[b * 5 + p] = e[p] * inv;
    }
}

extern "C" void kernel_launch(void* const* d_in, const int* in_sizes, int n_in,
                              void* d_out, int out_size)
{
    const float* x    = (const float*)d_in[0];
    const float* h0   = (const float*)d_in[1];
    const float* c0   = (const float*)d_in[2];
    const float* WihF = (const float*)d_in[3];
    const float* WhhF = (const float*)d_in[4];
    const float* biF  = (const float*)d_in[5];
    const float* bhF  = (const float*)d_in[6];
    const float* WihB = (const float*)d_in[7];
    const float* WhhB = (const float*)d_in[8];
    const float* biB  = (const float*)d_in[9];
    const float* bhB  = (const float*)d_in[10];
    const float* W1   = (const float*)d_in[11];
    const float* b1   = (const float*)d_in[12];
    const float* W2   = (const float*)d_in[13];
    const float* b2   = (const float*)d_in[14];
    float* out = (float*)d_out;

    const int tot = 2 * NR * HID;
    k_init<<<(tot + 255) / 256, 256>>>(h0, c0);

    dim3 ggrid(G4 / 128, NR / 128, 2);   // (8, 40, 2)
    for (int t = 0; t < SEQ; t++) {
        k_gemm<<<ggrid, 256>>>(x, WihF, WhhF, WihB, WhhB, t);
        k_update<<<(tot + 255) / 256, 256>>>(biF, bhF, biB, bhB);
    }

    k_xfea<<<(NR * HID + 255) / 256, 256>>>(out + BATCH * 5);
    k_head<<<BATCH, 64>>>(W1, b1, W2, b2, out);
}

// round 2
// speedup vs baseline: 1.8174x; 1.8174x over previous
#include <cuda_runtime.h>
#include <cuda_bf16.h>
#include <mma.h>
#include <math.h>

using namespace nvcuda;

// Problem constants
#define NR    5120        // LSTM batch (512*10)
#define HID   256
#define G4    1024        // 4*HID
#define SEQ   30
#define INP   100
#define BATCH 512
#define KSPL  1152        // 3*128 (x zones) + 3*256 (h zones)
#define KC    64          // K chunk per SMEM stage

// Persistent state / scratch (re-initialized inside the graph each replay)
__device__ __nv_bfloat16 g_xhi[NR * SEQ * INP];
__device__ __nv_bfloat16 g_xlo[NR * SEQ * INP];
__device__ __nv_bfloat16 g_Bsplit[2][KSPL * G4];
__device__ __nv_bfloat16 g_hhi[2][NR * HID];
__device__ __nv_bfloat16 g_hlo[2][NR * HID];
__device__ float g_hf[2][NR * HID];
__device__ float g_c[2][NR * HID];
__device__ float g_gates[2][NR * G4];

// ---------------- precompute: split x into bf16 hi/lo ----------------
__global__ void k_split_x(const float* __restrict__ x) {
    int i = blockIdx.x * blockDim.x + threadIdx.x;
    if (i >= NR * SEQ * INP) return;
    float v = x[i];
    __nv_bfloat16 hi = __float2bfloat16(v);
    g_xhi[i] = hi;
    g_xlo[i] = __float2bfloat16(v - __bfloat162float(hi));
}

// ---------------- precompute: build interleaved split weight panel ----------------
// B'[dir][k][n], k zones: [0,128)=Wih_hi, [128,256)=Wih_lo, [256,384)=Wih_hi (k_local>=100 -> 0)
//                          [384,640)=Whh_hi, [640,896)=Whh_lo, [896,1152)=Whh_hi
__global__ void k_split_w(const float* __restrict__ WihF, const float* __restrict__ WhhF,
                          const float* __restrict__ WihB, const float* __restrict__ WhhB) {
    int i = blockIdx.x * blockDim.x + threadIdx.x;
    if (i >= 2 * KSPL * G4) return;
    int dir = i / (KSPL * G4);
    int r   = i - dir * (KSPL * G4);
    int k   = r >> 10;         // 0..1151
    int n   = r & 1023;
    const float* Wih = dir ? WihB : WihF;
    const float* Whh = dir ? WhhB : WhhF;
    float w;
    bool want_lo;
    if (k < 384) {
        int off = k & 127;
        w = (off < 100) ? Wih[n * INP + off] : 0.f;
        want_lo = (k >= 128 && k < 256);
    } else {
        int kh = k - 384;
        int off = kh & 255;
        w = Whh[n * HID + off];
        want_lo = (kh >= 256 && kh < 512);
    }
    __nv_bfloat16 hi = __float2bfloat16(w);
    g_Bsplit[dir][r] = want_lo ? __float2bfloat16(w - __bfloat162float(hi)) : hi;
}

// ---------------- init state ----------------
__global__ void k_init(const float* __restrict__ h0, const float* __restrict__ c0) {
    int i = blockIdx.x * blockDim.x + threadIdx.x;
    if (i >= 2 * NR * HID) return;
    float h = h0[i];
    __nv_bfloat16 hi = __float2bfloat16(h);
    ((__nv_bfloat16*)g_hhi)[i] = hi;
    ((__nv_bfloat16*)g_hlo)[i] = __float2bfloat16(h - __bfloat162float(hi));
    ((float*)g_hf)[i] = h;
    ((float*)g_c)[i] = c0[i];
}

// ---------------- per-step gate GEMM (WMMA bf16, fp32 accum) ----------------
// gates[dir] = A'[NR x 1152] @ B'[1152 x 1024], CTA tile 128x128, 8 warps (4m x 2n),
// warp tile 32x64.
__global__ __launch_bounds__(256) void k_gemm_mma(int step) {
    const int dir = blockIdx.z;
    const __nv_bfloat16* __restrict__ Bsp = g_Bsplit[dir];
    const __nv_bfloat16* __restrict__ hhi = g_hhi[dir];
    const __nv_bfloat16* __restrict__ hlo = g_hlo[dir];
    const int tx = dir ? (SEQ - 1 - step) : step;

    __shared__ __nv_bfloat16 As[128][KC + 16];   // lda = 80
    __shared__ __nv_bfloat16 Bs[KC][128 + 16];   // ldb = 144

    const int row0 = blockIdx.y * 128;
    const int col0 = blockIdx.x * 128;
    const int tid  = threadIdx.x;
    const int wid  = tid >> 5;
    const int warp_m = wid & 3;       // 0..3  -> 32 rows each
    const int warp_n = wid >> 2;      // 0..1  -> 64 cols each

    wmma::fragment<wmma::accumulator, 16, 16, 16, float> acc[2][4];
#pragma unroll
    for (int i = 0; i < 2; i++)
#pragma unroll
        for (int j = 0; j < 4; j++) wmma::fill_fragment(acc[i][j], 0.f);

    for (int k0 = 0; k0 < KSPL; k0 += KC) {
        // --- load A tile: 128 rows x 64 k = 8192 bf16, 8 x uint2 per thread ---
#pragma unroll
        for (int p = 0; p < 8; p++) {
            int gid = tid + p * 256;
            int r   = gid >> 4;           // 16 groups-of-4 per row
            int kg  = (gid & 15) << 2;
            int k   = k0 + kg;
            int n   = row0 + r;
            uint2 v = make_uint2(0u, 0u);
            if (k < 384) {
                int off = k & 127;
                const __nv_bfloat16* src = (k < 256) ? g_xhi : g_xlo;
                if (off < 100)
                    v = *(const uint2*)&src[n * (SEQ * INP) + tx * INP + off];
            } else {
                int kh  = k - 384;
                int off = kh & 255;
                const __nv_bfloat16* src = (kh < 512) ? hhi : hlo;
                v = *(const uint2*)&src[n * HID + off];
            }
            *(uint2*)&As[r][kg] = v;
        }
        // --- load B tile: 64 k x 128 cols ---
#pragma unroll
        for (int p = 0; p < 8; p++) {
            int gid = tid + p * 256;
            int r   = gid >> 5;           // 32 groups-of-4 per row
            int cg  = (gid & 31) << 2;
            uint2 v = *(const uint2*)&Bsp[(k0 + r) * G4 + col0 + cg];
            *(uint2*)&Bs[r][cg] = v;
        }
        __syncthreads();

#pragma unroll
        for (int kk = 0; kk < KC; kk += 16) {
            wmma::fragment<wmma::matrix_a, 16, 16, 16, __nv_bfloat16, wmma::row_major> af[2];
            wmma::fragment<wmma::matrix_b, 16, 16, 16, __nv_bfloat16, wmma::row_major> bf[4];
#pragma unroll
            for (int i = 0; i < 2; i++)
                wmma::load_matrix_sync(af[i], &As[warp_m * 32 + i * 16][kk], KC + 16);
#pragma unroll
            for (int j = 0; j < 4; j++)
                wmma::load_matrix_sync(bf[j], &Bs[kk][warp_n * 64 + j * 16], 128 + 16);
#pragma unroll
            for (int i = 0; i < 2; i++)
#pragma unroll
                for (int j = 0; j < 4; j++)
                    wmma::mma_sync(acc[i][j], af[i], bf[j], acc[i][j]);
        }
        __syncthreads();
    }

    float* __restrict__ out = g_gates[dir];
#pragma unroll
    for (int i = 0; i < 2; i++)
#pragma unroll
        for (int j = 0; j < 4; j++)
            wmma::store_matrix_sync(
                &out[(row0 + warp_m * 32 + i * 16) * G4 + col0 + warp_n * 64 + j * 16],
                acc[i][j], G4, wmma::mem_row_major);
}

__device__ __forceinline__ float sigm(float v) { return 1.f / (1.f + expf(-v)); }

// ---------------- pointwise LSTM cell update ----------------
__global__ void k_update(const float* __restrict__ biF, const float* __restrict__ bhF,
                         const float* __restrict__ biB, const float* __restrict__ bhB)
{
    int idx = blockIdx.x * blockDim.x + threadIdx.x;
    if (idx >= 2 * NR * HID) return;
    int dir = idx / (NR * HID);
    int r   = idx - dir * (NR * HID);
    int n   = r >> 8;
    int hc  = r & 255;
    const float* __restrict__ gt = g_gates[dir] + n * G4;
    const float* __restrict__ bi = dir ? biB : biF;
    const float* __restrict__ bh = dir ? bhB : bhF;
    float gi = gt[hc]       + bi[hc]       + bh[hc];
    float gf = gt[hc + 256] + bi[hc + 256] + bh[hc + 256];
    float gg = gt[hc + 512] + bi[hc + 512] + bh[hc + 512];
    float go = gt[hc + 768] + bi[hc + 768] + bh[hc + 768];
    float c = g_c[dir][r];
    c = sigm(gf) * c + sigm(gi) * tanhf(gg);
    g_c[dir][r] = c;
    float h = sigm(go) * tanhf(c);
    g_hf[dir][r] = h;
    __nv_bfloat16 hi = __float2bfloat16(h);
    g_hhi[dir][r] = hi;
    g_hlo[dir][r] = __float2bfloat16(h - __bfloat162float(hi));
}

// x_fea[b, j, k] = k<128 ? hF[n, k] : hB[n, k]   (n = b*10+j, k in [0,256))
__global__ void k_xfea(float* __restrict__ out_xfea) {
    int idx = blockIdx.x * blockDim.x + threadIdx.x;
    if (idx >= NR * HID) return;
    int k = idx & 255;
    int n = idx >> 8;
    out_xfea[idx] = (k < 128) ? g_hf[0][n * HID + k] : g_hf[1][n * HID + k];
}

// ---------------- head ----------------
__global__ __launch_bounds__(64) void k_head(
    const float* __restrict__ W1, const float* __restrict__ b1,
    const float* __restrict__ W2, const float* __restrict__ b2,
    float* __restrict__ out)
{
    int b = blockIdx.x;
    int u = threadIdx.x;
    const float* __restrict__ flat = out + BATCH * 5 + b * 2560;
    __shared__ float z[64];
    __shared__ float logit[5];

    float acc = b1[u];
    const float* __restrict__ w = W1 + u * 2560;
#pragma unroll 4
    for (int v = 0; v < 2560; v++)
        acc = fmaf(flat[v], w[v], acc);
    z[u] = acc;
    __syncthreads();

    if (u < 5) {
        float a = b2[u];
#pragma unroll
        for (int j = 0; j < 64; j++)
            a = fmaf(z[j], W2[u * 64 + j], a);
        logit[u] = a;
    }
    __syncthreads();

    if (u == 0) {
        float m = logit[0];
#pragma unroll
        for (int p = 1; p < 5; p++) m = fmaxf(m, logit[p]);
        float e[5], s = 0.f;
#pragma unroll
        for (int p = 0; p < 5; p++) { e[p] = expf(logit[p] - m); s += e[p]; }
        float inv = 1.f / s;
#pragma unroll
        for (int p = 0; p < 5; p++) out[b * 5 + p] = e[p] * inv;
    }
}

extern "C" void kernel_launch(void* const* d_in, const int* in_sizes, int n_in,
                              void* d_out, int out_size)
{
    const float* x    = (const float*)d_in[0];
    const float* h0   = (const float*)d_in[1];
    const float* c0   = (const float*)d_in[2];
    const float* WihF = (const float*)d_in[3];
    const float* WhhF = (const float*)d_in[4];
    const float* biF  = (const float*)d_in[5];
    const float* bhF  = (const float*)d_in[6];
    const float* WihB = (const float*)d_in[7];
    const float* WhhB = (const float*)d_in[8];
    const float* biB  = (const float*)d_in[9];
    const float* bhB  = (const float*)d_in[10];
    const float* W1   = (const float*)d_in[11];
    const float* b1   = (const float*)d_in[12];
    const float* W2   = (const float*)d_in[13];
    const float* b2   = (const float*)d_in[14];
    float* out = (float*)d_out;

    k_split_x<<<(NR * SEQ * INP + 255) / 256, 256>>>(x);
    k_split_w<<<(2 * KSPL * G4 + 255) / 256, 256>>>(WihF, WhhF, WihB, WhhB);
    const int tot = 2 * NR * HID;
    k_init<<<(tot + 255) / 256, 256>>>(h0, c0);

    dim3 ggrid(G4 / 128, NR / 128, 2);   // (8, 40, 2)
    for (int t = 0; t < SEQ; t++) {
        k_gemm_mma<<<ggrid, 256>>>(t);
        k_update<<<(tot + 255) / 256, 256>>>(biF, bhF, biB, bhB);
    }

    k_xfea<<<(NR * HID + 255) / 256, 256>>>(out + BATCH * 5);
    k_head<<<BATCH, 64>>>(W1, b1, W2, b2, out);
}

// round 7
// speedup vs baseline: 3.2461x; 1.7861x over previous
#include <cuda_runtime.h>
#include <cuda_bf16.h>
#include <mma.h>
#include <math.h>
#include <stdint.h>

using namespace nvcuda;

// ---------------------------------------------------------------- constants
#define NR    5120
#define HID   256
#define G4    1024
#define SEQ   30
#define INP   100
#define BATCH 512
#define KTOT  1152        // 384 (x zones) + 768 (h zones)
#define NCH   18          // K chunks of 64
#define ASZ   18432       // A stage: 128 rows x 72 halves x 2B
#define BSZ   17408       // B stage: 64 rows x 136 halves x 2B
#define STAGEB (ASZ + BSZ)          // 35840
#define SMEM_DYN (3 * STAGEB)       // 107520

// ---------------------------------------------------------------- panels
__device__ __align__(16) __nv_bfloat16 g_Apx[(size_t)SEQ * NR * 384]; // [t][n][k]
__device__ __align__(16) __nv_bfloat16 g_Aph[(size_t)2 * NR * 768];   // [dir][n][k]
__device__ __align__(16) __nv_bfloat16 g_Bp[(size_t)2 * KTOT * G4];   // [dir][k][col']
__device__ float g_c [(size_t)2 * NR * HID];   // [dir][n][hc]
__device__ float g_hf[(size_t)2 * NR * HID];   // [dir][n][hc]
__device__ float g_bias[2][G4];                // permuted combined bias

// ---------------------------------------------------------------- helpers
__device__ __forceinline__ uint32_t smem_u32(const void* p) {
    return (uint32_t)__cvta_generic_to_shared((void*)p);
}
__device__ __forceinline__ void cpasync16(uint32_t dst, const void* src) {
    asm volatile("cp.async.cg.shared.global [%0], [%1], 16;"
        :: "r"(dst), "l"(__cvta_generic_to_global(src)) : "memory");
}
__device__ __forceinline__ void cpcommit() {
    asm volatile("cp.async.commit_group;" ::: "memory");
}
template<int N> __device__ __forceinline__ void cpwait() {
    asm volatile("cp.async.wait_group %0;" :: "n"(N) : "memory");
}
__device__ __forceinline__ float sigm(float v) {
    return __fdividef(1.f, 1.f + __expf(-v));
}
__device__ __forceinline__ float tanh_(float v) {
    return __fdividef(2.f, 1.f + __expf(-2.f * v)) - 1.f;
}

// ---------------------------------------------------------------- pack x panel
// zones: [0,128) x_hi (pairs Wih_hi), [128,256) x_hi (pairs Wih_lo), [256,384) x_lo (pairs Wih_hi)
__global__ void k_packx(const float* __restrict__ x) {
    size_t idx = (size_t)blockIdx.x * blockDim.x + threadIdx.x;
    if (idx >= (size_t)SEQ * NR * 384) return;
    int k = idx % 384;
    size_t r = idx / 384;
    int n = r % NR;
    int t = r / NR;
    int col = k & 127;
    bool lo = (k >= 256);
    float w = (col < INP) ? x[((size_t)n * SEQ + t) * INP + col] : 0.f;
    __nv_bfloat16 hi = __float2bfloat16(w);
    g_Apx[idx] = lo ? __float2bfloat16(w - __bfloat162float(hi)) : hi;
}

// ---------------------------------------------------------------- pack B panel
// k zones: [0,128) Wih_hi, [128,256) Wih_lo, [256,384) Wih_hi,
//          [384,640) Whh_hi, [640,896) Whh_lo, [896,1152) Whh_hi
// col' = hc*4 + gate; source weight row = gate*256 + hc
__global__ void k_packB(const float* __restrict__ WihF, const float* __restrict__ WhhF,
                        const float* __restrict__ WihB, const float* __restrict__ WhhB) {
    size_t idx = (size_t)blockIdx.x * blockDim.x + threadIdx.x;
    if (idx >= (size_t)2 * KTOT * G4) return;
    int col = idx % G4;
    size_t r = idx / G4;
    int k = r % KTOT;
    int dir = r / KTOT;
    const float* Wih = dir ? WihB : WihF;
    const float* Whh = dir ? WhhB : WhhF;
    int srow = (col & 3) * 256 + (col >> 2);
    float w; bool lo;
    if (k < 384) {
        int kk = k & 127;
        w = (kk < INP) ? Wih[srow * INP + kk] : 0.f;
        lo = (k >= 128 && k < 256);
    } else {
        int kh = k - 384;
        w = Whh[srow * HID + (kh & 255)];
        lo = (kh >= 256 && kh < 512);
    }
    __nv_bfloat16 hi = __float2bfloat16(w);
    g_Bp[idx] = lo ? __float2bfloat16(w - __bfloat162float(hi)) : hi;
}

// ---------------------------------------------------------------- combined bias (permuted)
__global__ void k_bias(const float* __restrict__ biF, const float* __restrict__ bhF,
                       const float* __restrict__ biB, const float* __restrict__ bhB) {
    int idx = blockIdx.x * blockDim.x + threadIdx.x;
    if (idx >= 2 * G4) return;
    int dir = idx >> 10;
    int col = idx & 1023;
    int src = (col & 3) * 256 + (col >> 2);
    g_bias[dir][col] = dir ? (biB[src] + bhB[src]) : (biF[src] + bhF[src]);
}

// ---------------------------------------------------------------- init state (h panel + c)
__global__ void k_init(const float* __restrict__ h0, const float* __restrict__ c0) {
    int idx = blockIdx.x * blockDim.x + threadIdx.x;
    if (idx >= 2 * NR * HID) return;
    int hc = idx & 255;
    size_t r = idx >> 8;          // dir*NR + n
    float h = h0[idx];
    g_c[idx] = c0[idx];
    __nv_bfloat16 hi = __float2bfloat16(h);
    __nv_bfloat16 lo = __float2bfloat16(h - __bfloat162float(hi));
    size_t hb = r * 768;
    g_Aph[hb + hc] = hi;
    g_Aph[hb + 256 + hc] = hi;
    g_Aph[hb + 512 + hc] = lo;
}

// ---------------------------------------------------------------- fused step GEMM + cell update
// grid (8, 40, 2), 128 threads. CTA tile 128M x 128N, warp tile 64x64.
__global__ __launch_bounds__(128) void k_step(int t) {
    extern __shared__ char dyn[];
    __shared__ float sbias[128];

    const int nt = blockIdx.x, mt = blockIdx.y, dir = blockIdx.z;
    const int tx = dir ? (SEQ - 1 - t) : t;
    const int tid = threadIdx.x;
    const int wid = tid >> 5;
    const int wm = wid & 1, wn = wid >> 1;
    const int col0 = nt * 128, row0 = mt * 128;

    sbias[tid] = g_bias[dir][col0 + tid];

    const __nv_bfloat16* Apx = g_Apx + ((size_t)tx * NR + row0) * 384;
    const __nv_bfloat16* Aph = g_Aph + ((size_t)dir * NR + row0) * 768;
    const __nv_bfloat16* Bp  = g_Bp + (size_t)dir * KTOT * G4;

    wmma::fragment<wmma::accumulator, 16, 16, 16, float> acc[4][4];
#pragma unroll
    for (int i = 0; i < 4; i++)
#pragma unroll
        for (int j = 0; j < 4; j++) wmma::fill_fragment(acc[i][j], 0.f);

    // ---- async fill of one stage ----
    auto issue = [&](int c) {
        int s = c % 3;
        char* As = dyn + s * STAGEB;
        char* Bs = As + ASZ;
#pragma unroll
        for (int i = 0; i < 8; i++) {          // A: 128 rows x 64 k
            int u = tid + i * 128;
            int r = u >> 3, kc = u & 7;
            const __nv_bfloat16* src = (c < 6)
                ? Apx + (size_t)r * 384 + c * 64 + kc * 8
                : Aph + (size_t)r * 768 + (c - 6) * 64 + kc * 8;
            cpasync16(smem_u32(As + r * 144 + kc * 16), src);
        }
#pragma unroll
        for (int i = 0; i < 8; i++) {          // B: 64 k x 128 cols
            int u = tid + i * 128;
            int r = u >> 4, nc = u & 15;
            const __nv_bfloat16* src = Bp + (size_t)(c * 64 + r) * G4 + col0 + nc * 8;
            cpasync16(smem_u32(Bs + r * 272 + nc * 16), src);
        }
        cpcommit();
    };

    issue(0); issue(1);

    for (int c = 0; c < NCH; c++) {
        __syncthreads();                        // prior compute done before overwrite
        if (c + 2 < NCH) issue(c + 2);
        if (c < NCH - 2)      cpwait<2>();
        else if (c == NCH - 2) cpwait<1>();
        else                   cpwait<0>();
        __syncthreads();

        int s = c % 3;
        const __nv_bfloat16* As = (const __nv_bfloat16*)(dyn + s * STAGEB);
        const __nv_bfloat16* Bs = (const __nv_bfloat16*)(dyn + s * STAGEB + ASZ);
#pragma unroll
        for (int kk = 0; kk < 64; kk += 16) {
            wmma::fragment<wmma::matrix_a, 16, 16, 16, __nv_bfloat16, wmma::row_major> a[4];
            wmma::fragment<wmma::matrix_b, 16, 16, 16, __nv_bfloat16, wmma::row_major> b[4];
#pragma unroll
            for (int i = 0; i < 4; i++)
                wmma::load_matrix_sync(a[i], As + (wm * 64 + i * 16) * 72 + kk, 72);
#pragma unroll
            for (int j = 0; j < 4; j++)
                wmma::load_matrix_sync(b[j], Bs + kk * 136 + wn * 64 + j * 16, 136);
#pragma unroll
            for (int i = 0; i < 4; i++)
#pragma unroll
                for (int j = 0; j < 4; j++)
                    wmma::mma_sync(acc[i][j], a[i], b[j], acc[i][j]);
        }
    }

    // ---- epilogue: C -> smem -> cell update -> h panel / c ----
    __syncthreads();
    float* Cs = (float*)dyn;                    // [128][132] fp32 (reuses stages 0/1)
#pragma unroll
    for (int i = 0; i < 4; i++)
#pragma unroll
        for (int j = 0; j < 4; j++)
            wmma::store_matrix_sync(Cs + (wm * 64 + i * 16) * 132 + wn * 64 + j * 16,
                                    acc[i][j], 132, wmma::mem_row_major);
    __syncthreads();

    const int hcl  = tid & 31;                  // local hc within col tile
    const int rblk = tid >> 5;
    const int hc   = nt * 32 + hcl;
    const bool last = (t == SEQ - 1);
#pragma unroll 4
    for (int i = 0; i < 32; i++) {
        int row = rblk * 32 + i;
        int n = row0 + row;
        const float* cr = Cs + row * 132 + hcl * 4;
        float gi = cr[0] + sbias[hcl * 4 + 0];
        float gf = cr[1] + sbias[hcl * 4 + 1];
        float gg = cr[2] + sbias[hcl * 4 + 2];
        float go = cr[3] + sbias[hcl * 4 + 3];
        size_t ci = ((size_t)dir * NR + n) * HID + hc;
        float c_ = g_c[ci];
        c_ = sigm(gf) * c_ + sigm(gi) * tanh_(gg);
        g_c[ci] = c_;
        float h = sigm(go) * tanh_(c_);
        if (last) g_hf[ci] = h;
        __nv_bfloat16 hi = __float2bfloat16(h);
        __nv_bfloat16 lo = __float2bfloat16(h - __bfloat162float(hi));
        size_t hb = ((size_t)dir * NR + n) * 768;
        g_Aph[hb + hc] = hi;
        g_Aph[hb + 256 + hc] = hi;
        g_Aph[hb + 512 + hc] = lo;
    }
}

// ---------------------------------------------------------------- x_fea assembly
__global__ void k_xfea(float* __restrict__ out_xfea) {
    int idx = blockIdx.x * blockDim.x + threadIdx.x;
    if (idx >= NR * HID) return;
    int k = idx & 255;
    out_xfea[idx] = (k < 128) ? g_hf[idx] : g_hf[(size_t)NR * HID + idx];
}

// ---------------------------------------------------------------- head
__global__ __launch_bounds__(64) void k_head(
    const float* __restrict__ W1, const float* __restrict__ b1,
    const float* __restrict__ W2, const float* __restrict__ b2,
    float* __restrict__ out)
{
    int b = blockIdx.x;
    int u = threadIdx.x;
    const float* __restrict__ flat = out + BATCH * 5 + b * 2560;
    __shared__ float z[64];
    __shared__ float logit[5];

    float acc = b1[u];
    const float* __restrict__ w = W1 + u * 2560;
#pragma unroll 4
    for (int v = 0; v < 2560; v++)
        acc = fmaf(flat[v], w[v], acc);
    z[u] = acc;
    __syncthreads();

    if (u < 5) {
        float a = b2[u];
#pragma unroll
        for (int j = 0; j < 64; j++)
            a = fmaf(z[j], W2[u * 64 + j], a);
        logit[u] = a;
    }
    __syncthreads();

    if (u == 0) {
        float m = logit[0];
#pragma unroll
        for (int p = 1; p < 5; p++) m = fmaxf(m, logit[p]);
        float e[5], s = 0.f;
#pragma unroll
        for (int p = 0; p < 5; p++) { e[p] = expf(logit[p] - m); s += e[p]; }
        float inv = 1.f / s;
#pragma unroll
        for (int p = 0; p < 5; p++) out[b * 5 + p] = e[p] * inv;
    }
}

// ---------------------------------------------------------------- launcher
extern "C" void kernel_launch(void* const* d_in, const int* in_sizes, int n_in,
                              void* d_out, int out_size)
{
    const float* x    = (const float*)d_in[0];
    const float* h0   = (const float*)d_in[1];
    const float* c0   = (const float*)d_in[2];
    const float* WihF = (const float*)d_in[3];
    const float* WhhF = (const float*)d_in[4];
    const float* biF  = (const float*)d_in[5];
    const float* bhF  = (const float*)d_in[6];
    const float* WihB = (const float*)d_in[7];
    const float* WhhB = (const float*)d_in[8];
    const float* biB  = (const float*)d_in[9];
    const float* bhB  = (const float*)d_in[10];
    const float* W1   = (const float*)d_in[11];
    const float* b1   = (const float*)d_in[12];
    const float* W2   = (const float*)d_in[13];
    const float* b2   = (const float*)d_in[14];
    float* out = (float*)d_out;

    static bool attr_set = false;
    if (!attr_set) {
        cudaFuncSetAttribute(k_step, cudaFuncAttributeMaxDynamicSharedMemorySize, SMEM_DYN);
        attr_set = true;
    }

    size_t npx = (size_t)SEQ * NR * 384;
    k_packx<<<(unsigned)((npx + 255) / 256), 256>>>(x);
    size_t npb = (size_t)2 * KTOT * G4;
    k_packB<<<(unsigned)((npb + 255) / 256), 256>>>(WihF, WhhF, WihB, WhhB);
    k_bias<<<(2 * G4 + 255) / 256, 256>>>(biF, bhF, biB, bhB);
    k_init<<<(2 * NR * HID + 255) / 256, 256>>>(h0, c0);

    dim3 ggrid(G4 / 128, NR / 128, 2);   // (8, 40, 2)
    for (int t = 0; t < SEQ; t++)
        k_step<<<ggrid, 128, SMEM_DYN>>>(t);

    k_xfea<<<(NR * HID + 255) / 256, 256>>>(out + BATCH * 5);
    k_head<<<BATCH, 64>>>(W1, b1, W2, b2, out);
}